// round 16
// baseline (speedup 1.0000x reference)
#include <cuda_runtime.h>
#include <cuda_bf16.h>
#include <cstdint>

#define N_NODES 10000
#define N_EDGES 320000
#define N_GRAPHS 64
#define KCHEB 10
#define IN_C 128
#define HID_C 256
#define OUT_C 128
#define KD_MAX (KCHEB * HID_C)  // 2560
#define WLD 6400                // 1280 + 2560 + 2560 (weight k-stride)

// ---------------- scratch (static device globals; no allocs) ----------------
// Double-buffered Chebyshev stacks: fp32 (prop gather) + bf16 hi/lo (GEMM A).
__device__ float g_T0[(size_t)N_NODES * KD_MAX];
__device__ float g_T1[(size_t)N_NODES * KD_MAX];
__device__ __nv_bfloat16 g_A0hi[(size_t)N_NODES * KD_MAX];
__device__ __nv_bfloat16 g_A0lo[(size_t)N_NODES * KD_MAX];
__device__ __nv_bfloat16 g_A1hi[(size_t)N_NODES * KD_MAX];
__device__ __nv_bfloat16 g_A1lo[(size_t)N_NODES * KD_MAX];
__device__ __nv_bfloat16 g_Whi[(size_t)HID_C * WLD];  // all W^T hi [256][6400]
__device__ __nv_bfloat16 g_Wlo[(size_t)HID_C * WLD];
__device__ float g_acc[(size_t)N_NODES * HID_C];      // final layer output h
__device__ float g_deg[N_NODES];
__device__ float g_dis[N_NODES];
__device__ int   g_rowcnt[N_NODES];
__device__ int   g_rowptr[N_NODES + 1];
__device__ int   g_cursor[N_NODES];
__device__ int2  g_edge[N_EDGES];          // packed (src, w-bits) CSR by dst
__device__ int   g_is64;

// ---------------- helpers ----------------
__device__ __forceinline__ uint32_t smem_u32(const void* p) {
    uint32_t a;
    asm("{ .reg .u64 t; cvta.to.shared.u64 t, %1; cvt.u32.u64 %0, t; }" : "=r"(a) : "l"(p));
    return a;
}
__device__ __forceinline__ uint32_t sw64(uint32_t off) { return off ^ ((off >> 3) & 0x30); }

__device__ __forceinline__ void cp16(uint32_t dst, const void* src) {
    asm volatile("cp.async.cg.shared.global [%0], [%1], 16;" :: "r"(dst), "l"(src) : "memory");
}
#define CP_COMMIT() asm volatile("cp.async.commit_group;" ::: "memory")
#define CP_WAIT(N)  asm volatile("cp.async.wait_group %0;" :: "n"(N) : "memory")

__device__ __forceinline__ void ldsm4(uint32_t* r, uint32_t addr) {
    asm volatile("ldmatrix.sync.aligned.m8n8.x4.shared.b16 {%0,%1,%2,%3}, [%4];"
                 : "=r"(r[0]), "=r"(r[1]), "=r"(r[2]), "=r"(r[3]) : "r"(addr));
}
__device__ __forceinline__ void mma16816(float* c, const uint32_t* a, uint32_t b0, uint32_t b1) {
    asm volatile("mma.sync.aligned.m16n8k16.row.col.f32.bf16.bf16.f32 "
                 "{%0,%1,%2,%3}, {%4,%5,%6,%7}, {%8,%9}, {%0,%1,%2,%3};"
                 : "+f"(c[0]), "+f"(c[1]), "+f"(c[2]), "+f"(c[3])
                 : "r"(a[0]), "r"(a[1]), "r"(a[2]), "r"(a[3]), "r"(b0), "r"(b1));
}
__device__ __forceinline__ void split2(float v, __nv_bfloat16& h, __nv_bfloat16& l) {
    h = __float2bfloat16(v);
    l = __float2bfloat16(v - __bfloat162float(h));
}
__device__ __forceinline__ uint32_t packhl(__nv_bfloat16 a, __nv_bfloat16 b) {
    return (uint32_t)__bfloat16_as_ushort(a) | ((uint32_t)__bfloat16_as_ushort(b) << 16);
}

// ---------------- dtype handling ----------------
__device__ __forceinline__ int ld_edge(const int* __restrict__ w, int half, int e) {
    if (g_is64) return w[((size_t)half * N_EDGES + e) * 2];
    return w[half * N_EDGES + e];
}
__device__ __forceinline__ int ld_batch(const int* __restrict__ w, int n) {
    if (g_is64) return w[2 * n];
    return w[n];
}

// ---------------- prep kernels ----------------
__global__ void k_zero_detect(const int* __restrict__ ei_w) {
    int i = blockIdx.x * blockDim.x + threadIdx.x;
    if (i == 0) {  // int64 detect: odd words all zero iff int64 little-endian
        int all0 = 1;
        for (int j = 0; j < 64; j++)
            if (ei_w[2 * j + 1] != 0) all0 = 0;
        g_is64 = all0;
    }
    if (i < N_NODES) { g_deg[i] = 0.f; g_rowcnt[i] = 0; }
}
__global__ void k_count(const int* __restrict__ ei) {
    int e = blockIdx.x * blockDim.x + threadIdx.x;
    if (e >= N_EDGES) return;
    atomicAdd(&g_deg[ld_edge(ei, 0, e)], 1.f);
    atomicAdd(&g_rowcnt[ld_edge(ei, 1, e)], 1);
}
// single block: dis + exclusive scan of rowcnt
__global__ void k_scan_dis() {
    __shared__ int sums[1024];
    int tid = threadIdx.x;
    for (int i = tid; i < N_NODES; i += 1024) {
        float d = g_deg[i];
        g_dis[i] = (d > 0.f) ? rsqrtf(d) : 0.f;
    }
    const int per = (N_NODES + 1023) / 1024;
    int start = tid * per, local = 0;
    for (int i = 0; i < per; i++) { int idx = start + i; if (idx < N_NODES) local += g_rowcnt[idx]; }
    sums[tid] = local;
    __syncthreads();
    for (int off = 1; off < 1024; off <<= 1) {
        int v = 0;
        if (tid >= off) v = sums[tid - off];
        __syncthreads();
        if (tid >= off) sums[tid] += v;
        __syncthreads();
    }
    int prefix = (tid == 0) ? 0 : sums[tid - 1];
    for (int i = 0; i < per; i++) {
        int idx = start + i;
        if (idx < N_NODES) { g_rowptr[idx] = prefix; g_cursor[idx] = prefix; prefix += g_rowcnt[idx]; }
    }
    if (tid == 1023) g_rowptr[N_NODES] = sums[1023];
}
__global__ void k_fill(const int* __restrict__ ei) {
    int e = blockIdx.x * blockDim.x + threadIdx.x;
    if (e >= N_EDGES) return;
    int s = ld_edge(ei, 0, e);
    int d = ld_edge(ei, 1, e);
    int pos = atomicAdd(&g_cursor[d], 1);
    float w = -g_dis[s] * g_dis[d];
    g_edge[pos] = make_int2(s, __float_as_int(w));
}

// ---------------- weight split (all 3 layers) + x -> stack0 slot 0 (merged) ----------------
#define NSPLIT (HID_C * WLD)                 // 1,638,400
#define NCOPYX (N_NODES * IN_C)              // 1,280,000
__global__ void k_split_w_copy_x(const float* __restrict__ W0, const float* __restrict__ W1,
                                 const float* __restrict__ W2, const float* __restrict__ x) {
    int i = blockIdx.x * blockDim.x + threadIdx.x;
    if (i < NSPLIT) {
        int n = i / WLD, kk = i % WLD;
        const float* W;
        int k;
        if (kk < 1280) { W = W0; k = kk; }
        else if (kk < 3840) { W = W1; k = kk - 1280; }
        else { W = W2; k = kk - 3840; }
        __nv_bfloat16 h, l;
        split2(W[(size_t)k * HID_C + n], h, l);
        g_Whi[(size_t)n * WLD + kk] = h;
        g_Wlo[(size_t)n * WLD + kk] = l;
    }
    if (i < NCOPYX) {
        int n = i / IN_C, c = i % IN_C;
        float v = x[i];
        size_t idx = (size_t)n * (KCHEB * IN_C) + c;
        g_T0[idx] = v;
        __nv_bfloat16 h, l;
        split2(v, h, l);
        g_A0hi[idx] = h;
        g_A0lo[idx] = l;
    }
}

// ---------------- Chebyshev propagation: float4 gather, 4 nodes/block, unroll 16 ----------------
// blockDim = (C/4, 4); grid = N_NODES/4
__global__ void k_prop(int sel, int xoff, int yoff, int ooff, int ld, float alpha, float beta) {
    const float* T = sel ? g_T1 : g_T0;
    float* Tw = sel ? g_T1 : g_T0;
    __nv_bfloat16* Ahi = sel ? g_A1hi : g_A0hi;
    __nv_bfloat16* Alo = sel ? g_A1lo : g_A0lo;
    int n = blockIdx.x * 4 + threadIdx.y;
    int cx = threadIdx.x;                      // column quad index
    const float* Xb = T + xoff + 4 * cx;
    int beg = g_rowptr[n], end = g_rowptr[n + 1];
    int cnt = end - beg;
    float ax = 0.f, ay = 0.f, az = 0.f, aw = 0.f;
#pragma unroll 16
    for (int i = 0; i < cnt; i++) {
        int2 m = __ldg(&g_edge[beg + i]);
        float w = __int_as_float(m.y);
        const float4 v = *(const float4*)(Xb + (size_t)m.x * ld);
        ax += w * v.x; ay += w * v.y; az += w * v.z; aw += w * v.w;
    }
    float4 r = make_float4(alpha * ax, alpha * ay, alpha * az, alpha * aw);
    if (beta != 0.f) {
        float4 o = *(const float4*)(T + (size_t)n * ld + ooff + 4 * cx);
        r.x += beta * o.x; r.y += beta * o.y; r.z += beta * o.z; r.w += beta * o.w;
    }
    size_t idx = (size_t)n * ld + yoff + 4 * cx;
    *(float4*)(Tw + idx) = r;
    __nv_bfloat16 h0, l0, h1, l1, h2, l2, h3, l3;
    split2(r.x, h0, l0); split2(r.y, h1, l1); split2(r.z, h2, l2); split2(r.w, h3, l3);
    *(uint2*)(Ahi + idx) = make_uint2(packhl(h0, h1), packhl(h2, h3));
    *(uint2*)(Alo + idx) = make_uint2(packhl(l0, l1), packhl(l2, l3));
}

// ---------------- mma.sync GEMM: out = relu(stack[M,Kd] @ W + bias) ----------------
// BM=192, BN=128, K-chunk 32, SW64, 4 stages (prefetch depth 3, CP_WAIT(2)).
// 8 warps (4M x 2N). grid (2, 53).
// mode 0: write OTHER stack slot 0 (stride KD_MAX, fp32 + bf16 hi/lo). mode 1: write g_acc.
#define GM_BM 192
#define GM_AT_BYTES (GM_BM * 64)
#define GM_BT_BYTES (128 * 64)
#define GM_STAGE    (2 * GM_AT_BYTES + 2 * GM_BT_BYTES)  // 40960
#define GM_NSTAGES  4
#define GM_SMEM_TOTAL (GM_NSTAGES * GM_STAGE)            // 163840

__global__ void __launch_bounds__(256) k_gemm_mma(const float* __restrict__ bias,
                                                  int sel, int koff, int Kd, int mode) {
    extern __shared__ char smem[];
    uint32_t sbase = smem_u32(smem);
    int tid = threadIdx.x;
    int lane = tid & 31, wid = tid >> 5;
    int wm = wid & 3, wn = wid >> 2;

    int col0 = blockIdx.x * 128;
    int row0 = blockIdx.y * GM_BM;
    const int nchunks = Kd >> 5;

    const __nv_bfloat16* Ahi = sel ? g_A1hi : g_A0hi;
    const __nv_bfloat16* Alo = sel ? g_A1lo : g_A0lo;
    float* Tn = sel ? g_T0 : g_T1;                 // other stack (next layer input)
    __nv_bfloat16* Nhi = sel ? g_A0hi : g_A1hi;
    __nv_bfloat16* Nlo = sel ? g_A0lo : g_A1lo;
    const __nv_bfloat16* Bh = g_Whi + koff;
    const __nv_bfloat16* Bl = g_Wlo + koff;

    float acc[3][8][4];
#pragma unroll
    for (int a = 0; a < 3; a++)
#pragma unroll
        for (int b = 0; b < 8; b++)
#pragma unroll
            for (int cq = 0; cq < 4; cq++) acc[a][b][cq] = 0.f;

    auto load_stage = [&](int c) {
        uint32_t toff = sbase + (c % GM_NSTAGES) * GM_STAGE;
        int k0 = c << 5;
#pragma unroll
        for (int i = 0; i < 10; i++) {
            int u = i * 256 + tid;
            if (u < 1536) {                       // A tiles (hi, lo)
                int v = u;
                const __nv_bfloat16* src;
                uint32_t tb;
                if (v < 768) { src = Ahi; tb = 0; }
                else { src = Alo; v -= 768; tb = GM_AT_BYTES; }
                int r = v >> 2, q = v & 3;
                int ga = min(row0 + r, N_NODES - 1);
                cp16(toff + tb + sw64((uint32_t)(r * 64 + q * 16)),
                     src + (size_t)ga * Kd + k0 + q * 8);
            } else {                              // B tiles
                int v = u - 1536;
                const __nv_bfloat16* src;
                uint32_t tb;
                if (v < 512) { src = Bh; tb = 2 * GM_AT_BYTES; }
                else { src = Bl; v -= 512; tb = 2 * GM_AT_BYTES + GM_BT_BYTES; }
                int r = v >> 2, q = v & 3;
                int gb = col0 + r;
                cp16(toff + tb + sw64((uint32_t)(r * 64 + q * 16)),
                     src + (size_t)gb * WLD + k0 + q * 8);
            }
        }
        CP_COMMIT();
    };

    load_stage(0);
    if (nchunks > 1) load_stage(1);
    if (nchunks > 2) load_stage(2);

    int arow = lane & 15, ahalf = lane >> 4;

    for (int c = 0; c < nchunks; c++) {
        // outstanding groups ⊆ {c, c+1, c+2}; leave ≤2 pending -> stage c complete
        if (c + 2 < nchunks) { CP_WAIT(2); }
        else if (c + 1 < nchunks) { CP_WAIT(1); }
        else { CP_WAIT(0); }
        __syncthreads();
        if (c + 3 < nchunks) load_stage(c + 3);

        uint32_t toff = sbase + (c % GM_NSTAGES) * GM_STAGE;
        uint32_t offAhi = toff, offAlo = toff + GM_AT_BYTES;
        uint32_t offBhi = toff + 2 * GM_AT_BYTES, offBlo = offBhi + GM_BT_BYTES;

#pragma unroll
        for (int ks = 0; ks < 2; ks++) {
            uint32_t colb = (uint32_t)(ks * 32 + ahalf * 16);
            uint32_t ah[3][4], al[3][4];
#pragma unroll
            for (int mi = 0; mi < 3; mi++) {
                uint32_t so = sw64((uint32_t)((wm * 48 + mi * 16 + arow) * 64) + colb);
                ldsm4(ah[mi], offAhi + so);
                ldsm4(al[mi], offAlo + so);
            }
#pragma unroll
            for (int nb = 0; nb < 4; nb++) {
                uint32_t so = sw64((uint32_t)((wn * 64 + nb * 16 + arow) * 64) + colb);
                uint32_t bh[4], bl[4];
                ldsm4(bh, offBhi + so);
                ldsm4(bl, offBlo + so);
#pragma unroll
                for (int mi = 0; mi < 3; mi++) {
                    float* c0 = acc[mi][nb * 2 + 0];
                    float* c1 = acc[mi][nb * 2 + 1];
                    mma16816(c0, ah[mi], bh[0], bh[2]);
                    mma16816(c1, ah[mi], bh[1], bh[3]);
                    mma16816(c0, ah[mi], bl[0], bl[2]);
                    mma16816(c1, ah[mi], bl[1], bl[3]);
                    mma16816(c0, al[mi], bh[0], bh[2]);
                    mma16816(c1, al[mi], bh[1], bh[3]);
                }
            }
        }
        __syncthreads();
    }

    // epilogue: bias + relu -> next stack slot 0, or g_acc (final)
    int qr = lane >> 2, qc = (lane & 3) * 2;
#pragma unroll
    for (int mi = 0; mi < 3; mi++) {
#pragma unroll
        for (int nj = 0; nj < 8; nj++) {
            int gc = col0 + wn * 64 + nj * 8 + qc;
            float b0 = bias[gc], b1 = bias[gc + 1];
            float* cc = acc[mi][nj];
#pragma unroll
            for (int half = 0; half < 2; half++) {
                int gr = row0 + wm * 48 + mi * 16 + qr + half * 8;
                if (gr >= N_NODES) continue;
                float v0 = fmaxf(cc[half * 2 + 0] + b0, 0.f);
                float v1 = fmaxf(cc[half * 2 + 1] + b1, 0.f);
                if (mode == 0) {
                    size_t idx = (size_t)gr * KD_MAX + gc;
                    *(float2*)(Tn + idx) = make_float2(v0, v1);
                    __nv_bfloat16 h0, l0, h1, l1;
                    split2(v0, h0, l0);
                    split2(v1, h1, l1);
                    *(uint32_t*)(Nhi + idx) = packhl(h0, h1);
                    *(uint32_t*)(Nlo + idx) = packhl(l0, l1);
                } else {
                    *(float2*)&g_acc[(size_t)gr * HID_C + gc] = make_float2(v0, v1);
                }
            }
        }
    }
}

// ---------------- fused pool + output GEMM (batch is sorted) ----------------
__global__ void k_poolout(const int* __restrict__ batch, const float* __restrict__ Wout,
                          const float* __restrict__ bout, float* __restrict__ out) {
    int g = blockIdx.x, tid = threadIdx.x;  // 128 threads
    __shared__ float s_sum[HID_C];
    __shared__ int s_lo, s_hi;
    if (tid == 0) {
        int lo = 0, hi = N_NODES;
        while (lo < hi) { int m = (lo + hi) >> 1; if (ld_batch(batch, m) < g) lo = m + 1; else hi = m; }
        s_lo = lo;
        hi = N_NODES;
        while (lo < hi) { int m = (lo + hi) >> 1; if (ld_batch(batch, m) < g + 1) lo = m + 1; else hi = m; }
        s_hi = lo;
    }
    __syncthreads();
    int lo = s_lo, hi = s_hi;
    float a0 = 0.f, a1 = 0.f;
    for (int n = lo; n < hi; n++) {
        size_t o = (size_t)n * HID_C;
        a0 += g_acc[o + tid];
        a1 += g_acc[o + 128 + tid];
    }
    s_sum[tid] = a0;
    s_sum[128 + tid] = a1;
    __syncthreads();
    float inv = 1.f / fmaxf((float)(hi - lo), 1.f);
    float acc = 0.f;
    for (int k = 0; k < HID_C; k++)
        acc += s_sum[k] * Wout[(size_t)k * OUT_C + tid];
    out[g * OUT_C + tid] = acc * inv + bout[tid];
}

// ---------------- driver ----------------
extern "C" void kernel_launch(void* const* d_in, const int* in_sizes, int n_in,
                              void* d_out, int out_size) {
    const float* x = (const float*)d_in[0];
    const float* W0 = (const float*)d_in[1];
    const float* b0 = (const float*)d_in[2];
    const float* W1 = (const float*)d_in[3];
    const float* b1 = (const float*)d_in[4];
    const float* W2 = (const float*)d_in[5];
    const float* b2 = (const float*)d_in[6];
    const float* Wout = (const float*)d_in[7];
    const float* bout = (const float*)d_in[8];
    const int* ei = (const int*)d_in[9];
    const int* batch = (const int*)d_in[10];
    float* out = (float*)d_out;

    cudaFuncSetAttribute(k_gemm_mma, cudaFuncAttributeMaxDynamicSharedMemorySize, GM_SMEM_TOTAL);

    k_zero_detect<<<(N_NODES + 255) / 256, 256>>>(ei);
    k_count<<<(N_EDGES + 255) / 256, 256>>>(ei);
    k_scan_dis<<<1, 1024>>>();
    k_fill<<<(N_EDGES + 255) / 256, 256>>>(ei);
    k_split_w_copy_x<<<(NSPLIT + 255) / 256, 256>>>(W0, W1, W2, x);

    dim3 ggrid(2, (N_NODES + GM_BM - 1) / GM_BM);

    const int   sels[3] = {0, 1, 0};
    const int   Cs[3] = {IN_C, HID_C, HID_C};
    const int   Kds[3] = {KCHEB * IN_C, KCHEB * HID_C, KCHEB * HID_C};
    const int   wbase[3] = {0, 1280, 3840};
    const float* bs[3] = {b0, b1, b2};
    const int   modes[3] = {0, 0, 1};

    for (int L = 0; L < 3; L++) {
        int sel = sels[L], C = Cs[L], ld = Kds[L];
        dim3 pb(C / 4, 4);
        for (int k = 1; k < KCHEB; k++) {
            float alpha = (k == 1) ? 1.f : 2.f;
            float beta = (k >= 2) ? -1.f : 0.f;
            int ooff = (k >= 2) ? (k - 2) * C : 0;
            k_prop<<<N_NODES / 4, pb>>>(sel, (k - 1) * C, k * C, ooff, ld, alpha, beta);
        }
        k_gemm_mma<<<ggrid, 256, GM_SMEM_TOTAL>>>(bs[L], sel, wbase[L], ld, modes[L]);
    }

    k_poolout<<<N_GRAPHS, OUT_C>>>(batch, Wout, bout, out);
}

// round 17
// speedup vs baseline: 1.0179x; 1.0179x over previous
#include <cuda_runtime.h>
#include <cuda_bf16.h>
#include <cstdint>

#define N_NODES 10000
#define N_EDGES 320000
#define N_GRAPHS 64
#define KCHEB 10
#define IN_C 128
#define HID_C 256
#define OUT_C 128
#define KD_MAX (KCHEB * HID_C)  // 2560
#define WLD 6400                // 1280 + 2560 + 2560 (weight k-stride)

// ---------------- scratch (static device globals; no allocs) ----------------
// Double-buffered Chebyshev stacks: fp32 (prop gather) + bf16 hi/lo (GEMM A).
__device__ float g_T0[(size_t)N_NODES * KD_MAX];
__device__ float g_T1[(size_t)N_NODES * KD_MAX];
__device__ __nv_bfloat16 g_A0hi[(size_t)N_NODES * KD_MAX];
__device__ __nv_bfloat16 g_A0lo[(size_t)N_NODES * KD_MAX];
__device__ __nv_bfloat16 g_A1hi[(size_t)N_NODES * KD_MAX];
__device__ __nv_bfloat16 g_A1lo[(size_t)N_NODES * KD_MAX];
__device__ __nv_bfloat16 g_Whi[(size_t)HID_C * WLD];  // all W^T hi [256][6400]
__device__ __nv_bfloat16 g_Wlo[(size_t)HID_C * WLD];
__device__ float g_acc[(size_t)N_NODES * HID_C];      // final layer output h
__device__ float g_deg[N_NODES];
__device__ float g_dis[N_NODES];
__device__ int   g_rowcnt[N_NODES];
__device__ int   g_rowptr[N_NODES + 1];
__device__ int   g_cursor[N_NODES];
__device__ int2  g_edge[N_EDGES];          // packed (src, w-bits) CSR by dst
__device__ int   g_is64;

// ---------------- helpers ----------------
__device__ __forceinline__ uint32_t smem_u32(const void* p) {
    uint32_t a;
    asm("{ .reg .u64 t; cvta.to.shared.u64 t, %1; cvt.u32.u64 %0, t; }" : "=r"(a) : "l"(p));
    return a;
}
__device__ __forceinline__ uint32_t sw64(uint32_t off) { return off ^ ((off >> 3) & 0x30); }

__device__ __forceinline__ void cp16(uint32_t dst, const void* src) {
    asm volatile("cp.async.cg.shared.global [%0], [%1], 16;" :: "r"(dst), "l"(src) : "memory");
}
#define CP_COMMIT() asm volatile("cp.async.commit_group;" ::: "memory")
#define CP_WAIT(N)  asm volatile("cp.async.wait_group %0;" :: "n"(N) : "memory")

__device__ __forceinline__ void ldsm4(uint32_t* r, uint32_t addr) {
    asm volatile("ldmatrix.sync.aligned.m8n8.x4.shared.b16 {%0,%1,%2,%3}, [%4];"
                 : "=r"(r[0]), "=r"(r[1]), "=r"(r[2]), "=r"(r[3]) : "r"(addr));
}
__device__ __forceinline__ void mma16816(float* c, const uint32_t* a, uint32_t b0, uint32_t b1) {
    asm volatile("mma.sync.aligned.m16n8k16.row.col.f32.bf16.bf16.f32 "
                 "{%0,%1,%2,%3}, {%4,%5,%6,%7}, {%8,%9}, {%0,%1,%2,%3};"
                 : "+f"(c[0]), "+f"(c[1]), "+f"(c[2]), "+f"(c[3])
                 : "r"(a[0]), "r"(a[1]), "r"(a[2]), "r"(a[3]), "r"(b0), "r"(b1));
}
__device__ __forceinline__ void split2(float v, __nv_bfloat16& h, __nv_bfloat16& l) {
    h = __float2bfloat16(v);
    l = __float2bfloat16(v - __bfloat162float(h));
}
__device__ __forceinline__ uint32_t packhl(__nv_bfloat16 a, __nv_bfloat16 b) {
    return (uint32_t)__bfloat16_as_ushort(a) | ((uint32_t)__bfloat16_as_ushort(b) << 16);
}

// ---------------- dtype handling ----------------
__device__ __forceinline__ int ld_edge(const int* __restrict__ w, int half, int e) {
    if (g_is64) return w[((size_t)half * N_EDGES + e) * 2];
    return w[half * N_EDGES + e];
}
__device__ __forceinline__ int ld_batch(const int* __restrict__ w, int n) {
    if (g_is64) return w[2 * n];
    return w[n];
}

// ---------------- prep kernels ----------------
__global__ void k_zero_detect(const int* __restrict__ ei_w) {
    int i = blockIdx.x * blockDim.x + threadIdx.x;
    if (i == 0) {  // int64 detect: odd words all zero iff int64 little-endian
        int all0 = 1;
        for (int j = 0; j < 64; j++)
            if (ei_w[2 * j + 1] != 0) all0 = 0;
        g_is64 = all0;
    }
    if (i < N_NODES) { g_deg[i] = 0.f; g_rowcnt[i] = 0; }
}
__global__ void k_count(const int* __restrict__ ei) {
    int e = blockIdx.x * blockDim.x + threadIdx.x;
    if (e >= N_EDGES) return;
    atomicAdd(&g_deg[ld_edge(ei, 0, e)], 1.f);
    atomicAdd(&g_rowcnt[ld_edge(ei, 1, e)], 1);
}
// single block: dis + exclusive scan of rowcnt
__global__ void k_scan_dis() {
    __shared__ int sums[1024];
    int tid = threadIdx.x;
    for (int i = tid; i < N_NODES; i += 1024) {
        float d = g_deg[i];
        g_dis[i] = (d > 0.f) ? rsqrtf(d) : 0.f;
    }
    const int per = (N_NODES + 1023) / 1024;
    int start = tid * per, local = 0;
    for (int i = 0; i < per; i++) { int idx = start + i; if (idx < N_NODES) local += g_rowcnt[idx]; }
    sums[tid] = local;
    __syncthreads();
    for (int off = 1; off < 1024; off <<= 1) {
        int v = 0;
        if (tid >= off) v = sums[tid - off];
        __syncthreads();
        if (tid >= off) sums[tid] += v;
        __syncthreads();
    }
    int prefix = (tid == 0) ? 0 : sums[tid - 1];
    for (int i = 0; i < per; i++) {
        int idx = start + i;
        if (idx < N_NODES) { g_rowptr[idx] = prefix; g_cursor[idx] = prefix; prefix += g_rowcnt[idx]; }
    }
    if (tid == 1023) g_rowptr[N_NODES] = sums[1023];
}
__global__ void k_fill(const int* __restrict__ ei) {
    int e = blockIdx.x * blockDim.x + threadIdx.x;
    if (e >= N_EDGES) return;
    int s = ld_edge(ei, 0, e);
    int d = ld_edge(ei, 1, e);
    int pos = atomicAdd(&g_cursor[d], 1);
    float w = -g_dis[s] * g_dis[d];
    g_edge[pos] = make_int2(s, __float_as_int(w));
}

// ---------------- weight split (all 3 layers) + x -> stack0 slot 0 (merged) ----------------
#define NSPLIT (HID_C * WLD)                 // 1,638,400
#define NCOPYX (N_NODES * IN_C)              // 1,280,000
__global__ void k_split_w_copy_x(const float* __restrict__ W0, const float* __restrict__ W1,
                                 const float* __restrict__ W2, const float* __restrict__ x) {
    int i = blockIdx.x * blockDim.x + threadIdx.x;
    if (i < NSPLIT) {
        int n = i / WLD, kk = i % WLD;
        const float* W;
        int k;
        if (kk < 1280) { W = W0; k = kk; }
        else if (kk < 3840) { W = W1; k = kk - 1280; }
        else { W = W2; k = kk - 3840; }
        __nv_bfloat16 h, l;
        split2(W[(size_t)k * HID_C + n], h, l);
        g_Whi[(size_t)n * WLD + kk] = h;
        g_Wlo[(size_t)n * WLD + kk] = l;
    }
    if (i < NCOPYX) {
        int n = i / IN_C, c = i % IN_C;
        float v = x[i];
        size_t idx = (size_t)n * (KCHEB * IN_C) + c;
        g_T0[idx] = v;
        __nv_bfloat16 h, l;
        split2(v, h, l);
        g_A0hi[idx] = h;
        g_A0lo[idx] = l;
    }
}

// ---------------- Chebyshev propagation: float4 gather, 4 nodes/block, unroll 8 ----------------
// blockDim = (C/4, 4); grid = N_NODES/4
__global__ void k_prop(int sel, int xoff, int yoff, int ooff, int ld, float alpha, float beta) {
    const float* T = sel ? g_T1 : g_T0;
    float* Tw = sel ? g_T1 : g_T0;
    __nv_bfloat16* Ahi = sel ? g_A1hi : g_A0hi;
    __nv_bfloat16* Alo = sel ? g_A1lo : g_A0lo;
    int n = blockIdx.x * 4 + threadIdx.y;
    int cx = threadIdx.x;                      // column quad index
    const float* Xb = T + xoff + 4 * cx;
    int beg = g_rowptr[n], end = g_rowptr[n + 1];
    int cnt = end - beg;
    float ax = 0.f, ay = 0.f, az = 0.f, aw = 0.f;
#pragma unroll 8
    for (int i = 0; i < cnt; i++) {
        int2 m = __ldg(&g_edge[beg + i]);
        float w = __int_as_float(m.y);
        const float4 v = *(const float4*)(Xb + (size_t)m.x * ld);
        ax += w * v.x; ay += w * v.y; az += w * v.z; aw += w * v.w;
    }
    float4 r = make_float4(alpha * ax, alpha * ay, alpha * az, alpha * aw);
    if (beta != 0.f) {
        float4 o = *(const float4*)(T + (size_t)n * ld + ooff + 4 * cx);
        r.x += beta * o.x; r.y += beta * o.y; r.z += beta * o.z; r.w += beta * o.w;
    }
    size_t idx = (size_t)n * ld + yoff + 4 * cx;
    *(float4*)(Tw + idx) = r;
    __nv_bfloat16 h0, l0, h1, l1, h2, l2, h3, l3;
    split2(r.x, h0, l0); split2(r.y, h1, l1); split2(r.z, h2, l2); split2(r.w, h3, l3);
    *(uint2*)(Ahi + idx) = make_uint2(packhl(h0, h1), packhl(h2, h3));
    *(uint2*)(Alo + idx) = make_uint2(packhl(l0, l1), packhl(l2, l3));
}

// ---------------- mma.sync GEMM (R11/R14/R15-proven): out = relu(stack[M,Kd] @ W + bias) ----------------
// BM=192, BN=128, K-chunk 32, SW64, 3 stages; 8 warps (4M x 2N). grid (2, 53).
// mode 0: write OTHER stack slot 0 (stride KD_MAX, fp32 + bf16 hi/lo). mode 1: write g_acc.
#define GM_BM 192
#define GM_AT_BYTES (GM_BM * 64)
#define GM_BT_BYTES (128 * 64)
#define GM_STAGE    (2 * GM_AT_BYTES + 2 * GM_BT_BYTES)  // 40960
#define GM_NSTAGES  3
#define GM_SMEM_TOTAL (GM_NSTAGES * GM_STAGE)            // 122880

__global__ void __launch_bounds__(256) k_gemm_mma(const float* __restrict__ bias,
                                                  int sel, int koff, int Kd, int mode) {
    extern __shared__ char smem[];
    uint32_t sbase = smem_u32(smem);
    int tid = threadIdx.x;
    int lane = tid & 31, wid = tid >> 5;
    int wm = wid & 3, wn = wid >> 2;

    int col0 = blockIdx.x * 128;
    int row0 = blockIdx.y * GM_BM;
    const int nchunks = Kd >> 5;

    const __nv_bfloat16* Ahi = sel ? g_A1hi : g_A0hi;
    const __nv_bfloat16* Alo = sel ? g_A1lo : g_A0lo;
    float* Tn = sel ? g_T0 : g_T1;                 // other stack (next layer input)
    __nv_bfloat16* Nhi = sel ? g_A0hi : g_A1hi;
    __nv_bfloat16* Nlo = sel ? g_A0lo : g_A1lo;
    const __nv_bfloat16* Bh = g_Whi + koff;
    const __nv_bfloat16* Bl = g_Wlo + koff;

    float acc[3][8][4];
#pragma unroll
    for (int a = 0; a < 3; a++)
#pragma unroll
        for (int b = 0; b < 8; b++)
#pragma unroll
            for (int cq = 0; cq < 4; cq++) acc[a][b][cq] = 0.f;

    auto load_stage = [&](int c) {
        uint32_t toff = sbase + (c % GM_NSTAGES) * GM_STAGE;
        int k0 = c << 5;
#pragma unroll
        for (int i = 0; i < 10; i++) {
            int u = i * 256 + tid;
            if (u < 1536) {                       // A tiles (hi, lo)
                int v = u;
                const __nv_bfloat16* src;
                uint32_t tb;
                if (v < 768) { src = Ahi; tb = 0; }
                else { src = Alo; v -= 768; tb = GM_AT_BYTES; }
                int r = v >> 2, q = v & 3;
                int ga = min(row0 + r, N_NODES - 1);
                cp16(toff + tb + sw64((uint32_t)(r * 64 + q * 16)),
                     src + (size_t)ga * Kd + k0 + q * 8);
            } else {                              // B tiles
                int v = u - 1536;
                const __nv_bfloat16* src;
                uint32_t tb;
                if (v < 512) { src = Bh; tb = 2 * GM_AT_BYTES; }
                else { src = Bl; v -= 512; tb = 2 * GM_AT_BYTES + GM_BT_BYTES; }
                int r = v >> 2, q = v & 3;
                int gb = col0 + r;
                cp16(toff + tb + sw64((uint32_t)(r * 64 + q * 16)),
                     src + (size_t)gb * WLD + k0 + q * 8);
            }
        }
        CP_COMMIT();
    };

    load_stage(0);
    if (nchunks > 1) load_stage(1);

    int arow = lane & 15, ahalf = lane >> 4;

    for (int c = 0; c < nchunks; c++) {
        if (c + 1 < nchunks) { CP_WAIT(1); } else { CP_WAIT(0); }
        __syncthreads();
        if (c + 2 < nchunks) load_stage(c + 2);

        uint32_t toff = sbase + (c % GM_NSTAGES) * GM_STAGE;
        uint32_t offAhi = toff, offAlo = toff + GM_AT_BYTES;
        uint32_t offBhi = toff + 2 * GM_AT_BYTES, offBlo = offBhi + GM_BT_BYTES;

#pragma unroll
        for (int ks = 0; ks < 2; ks++) {
            uint32_t colb = (uint32_t)(ks * 32 + ahalf * 16);
            uint32_t ah[3][4], al[3][4];
#pragma unroll
            for (int mi = 0; mi < 3; mi++) {
                uint32_t so = sw64((uint32_t)((wm * 48 + mi * 16 + arow) * 64) + colb);
                ldsm4(ah[mi], offAhi + so);
                ldsm4(al[mi], offAlo + so);
            }
#pragma unroll
            for (int nb = 0; nb < 4; nb++) {
                uint32_t so = sw64((uint32_t)((wn * 64 + nb * 16 + arow) * 64) + colb);
                uint32_t bh[4], bl[4];
                ldsm4(bh, offBhi + so);
                ldsm4(bl, offBlo + so);
#pragma unroll
                for (int mi = 0; mi < 3; mi++) {
                    float* c0 = acc[mi][nb * 2 + 0];
                    float* c1 = acc[mi][nb * 2 + 1];
                    mma16816(c0, ah[mi], bh[0], bh[2]);
                    mma16816(c1, ah[mi], bh[1], bh[3]);
                    mma16816(c0, ah[mi], bl[0], bl[2]);
                    mma16816(c1, ah[mi], bl[1], bl[3]);
                    mma16816(c0, al[mi], bh[0], bh[2]);
                    mma16816(c1, al[mi], bh[1], bh[3]);
                }
            }
        }
        __syncthreads();
    }

    // epilogue: bias + relu -> next stack slot 0, or g_acc (final)
    int qr = lane >> 2, qc = (lane & 3) * 2;
#pragma unroll
    for (int mi = 0; mi < 3; mi++) {
#pragma unroll
        for (int nj = 0; nj < 8; nj++) {
            int gc = col0 + wn * 64 + nj * 8 + qc;
            float b0 = bias[gc], b1 = bias[gc + 1];
            float* cc = acc[mi][nj];
#pragma unroll
            for (int half = 0; half < 2; half++) {
                int gr = row0 + wm * 48 + mi * 16 + qr + half * 8;
                if (gr >= N_NODES) continue;
                float v0 = fmaxf(cc[half * 2 + 0] + b0, 0.f);
                float v1 = fmaxf(cc[half * 2 + 1] + b1, 0.f);
                if (mode == 0) {
                    size_t idx = (size_t)gr * KD_MAX + gc;
                    *(float2*)(Tn + idx) = make_float2(v0, v1);
                    __nv_bfloat16 h0, l0, h1, l1;
                    split2(v0, h0, l0);
                    split2(v1, h1, l1);
                    *(uint32_t*)(Nhi + idx) = packhl(h0, h1);
                    *(uint32_t*)(Nlo + idx) = packhl(l0, l1);
                } else {
                    *(float2*)&g_acc[(size_t)gr * HID_C + gc] = make_float2(v0, v1);
                }
            }
        }
    }
}

// ---------------- fused pool + output GEMM (batch is sorted) ----------------
__global__ void k_poolout(const int* __restrict__ batch, const float* __restrict__ Wout,
                          const float* __restrict__ bout, float* __restrict__ out) {
    int g = blockIdx.x, tid = threadIdx.x;  // 128 threads
    __shared__ float s_sum[HID_C];
    __shared__ int s_lo, s_hi;
    if (tid == 0) {
        int lo = 0, hi = N_NODES;
        while (lo < hi) { int m = (lo + hi) >> 1; if (ld_batch(batch, m) < g) lo = m + 1; else hi = m; }
        s_lo = lo;
        hi = N_NODES;
        while (lo < hi) { int m = (lo + hi) >> 1; if (ld_batch(batch, m) < g + 1) lo = m + 1; else hi = m; }
        s_hi = lo;
    }
    __syncthreads();
    int lo = s_lo, hi = s_hi;
    float a0 = 0.f, a1 = 0.f;
    for (int n = lo; n < hi; n++) {
        size_t o = (size_t)n * HID_C;
        a0 += g_acc[o + tid];
        a1 += g_acc[o + 128 + tid];
    }
    s_sum[tid] = a0;
    s_sum[128 + tid] = a1;
    __syncthreads();
    float inv = 1.f / fmaxf((float)(hi - lo), 1.f);
    float acc = 0.f;
    for (int k = 0; k < HID_C; k++)
        acc += s_sum[k] * Wout[(size_t)k * OUT_C + tid];
    out[g * OUT_C + tid] = acc * inv + bout[tid];
}

// ---------------- driver ----------------
extern "C" void kernel_launch(void* const* d_in, const int* in_sizes, int n_in,
                              void* d_out, int out_size) {
    const float* x = (const float*)d_in[0];
    const float* W0 = (const float*)d_in[1];
    const float* b0 = (const float*)d_in[2];
    const float* W1 = (const float*)d_in[3];
    const float* b1 = (const float*)d_in[4];
    const float* W2 = (const float*)d_in[5];
    const float* b2 = (const float*)d_in[6];
    const float* Wout = (const float*)d_in[7];
    const float* bout = (const float*)d_in[8];
    const int* ei = (const int*)d_in[9];
    const int* batch = (const int*)d_in[10];
    float* out = (float*)d_out;

    cudaFuncSetAttribute(k_gemm_mma, cudaFuncAttributeMaxDynamicSharedMemorySize, GM_SMEM_TOTAL);

    k_zero_detect<<<(N_NODES + 255) / 256, 256>>>(ei);
    k_count<<<(N_EDGES + 255) / 256, 256>>>(ei);
    k_scan_dis<<<1, 1024>>>();
    k_fill<<<(N_EDGES + 255) / 256, 256>>>(ei);
    k_split_w_copy_x<<<(NSPLIT + 255) / 256, 256>>>(W0, W1, W2, x);

    dim3 ggrid(2, (N_NODES + GM_BM - 1) / GM_BM);

    const int   sels[3] = {0, 1, 0};
    const int   Cs[3] = {IN_C, HID_C, HID_C};
    const int   Kds[3] = {KCHEB * IN_C, KCHEB * HID_C, KCHEB * HID_C};
    const int   wbase[3] = {0, 1280, 3840};
    const float* bs[3] = {b0, b1, b2};
    const int   modes[3] = {0, 0, 1};

    for (int L = 0; L < 3; L++) {
        int sel = sels[L], C = Cs[L], ld = Kds[L];
        dim3 pb(C / 4, 4);
        for (int k = 1; k < KCHEB; k++) {
            float alpha = (k == 1) ? 1.f : 2.f;
            float beta = (k >= 2) ? -1.f : 0.f;
            int ooff = (k >= 2) ? (k - 2) * C : 0;
            k_prop<<<N_NODES / 4, pb>>>(sel, (k - 1) * C, k * C, ooff, ld, alpha, beta);
        }
        k_gemm_mma<<<ggrid, 256, GM_SMEM_TOTAL>>>(bs[L], sel, wbase[L], ld, modes[L]);
    }

    k_poolout<<<N_GRAPHS, OUT_C>>>(batch, Wout, bout, out);
}